// round 5
// baseline (speedup 1.0000x reference)
#include <cuda_runtime.h>
#include <math.h>

// Problem constants
#define NN   32
#define CC   512
#define HH   56
#define WW   56
#define HW   (HH * WW)        // 3136
#define FF   8                // frequencies
#define OO   32               // C / R = 512/16
#define ROWS (NN * CC)        // 16384 (n,c) rows

// Scratch (no cudaMalloc allowed): intermediates live in device globals.
__device__ float g_y[NN * FF * CC];   // pooled DCT features, layout (n, f, c)
__device__ float g_s[NN * CC];        // per-(n,c) sigmoid scale

// ---------------------------------------------------------------------------
// Kernel 1: multi-frequency DCT pooling.
//   y[n,f,c] = sum_{hw} x[n,c,hw] * dct[f,hw]
// Strategy:
//   - whole DCT basis (8 x 3136 fp32 = 100,352 B) staged in dynamic smem
//   - 1 warp handles 4 consecutive (n,c) rows -> each smem read (LDS.128)
//     amortized over 4 rows x 4 elements => 8 B smem traffic / x element
//   - float4 global loads, fmaf chains, 32 independent accumulators for ILP
//   - butterfly-shuffle reduce at the end, lane 0 writes 32 results
// Grid: 512 blocks x 256 thr (8 warps x 4 rows = 32 rows/block; 512*32=16384)
// ---------------------------------------------------------------------------
__global__ __launch_bounds__(256, 2)
void freq_pool_kernel(const float* __restrict__ x,
                      const float* __restrict__ dct)
{
    extern __shared__ float sdct[];           // FF * HW floats

    // Cooperative load of the DCT basis (vectorized).
    {
        const float4* src = (const float4*)dct;
        float4*       dst = (float4*)sdct;
        const int n4 = FF * HW / 4;           // 6272
        for (int i = threadIdx.x; i < n4; i += blockDim.x)
            dst[i] = src[i];
    }
    __syncthreads();

    const int warp = threadIdx.x >> 5;
    const int lane = threadIdx.x & 31;
    const int row0 = (blockIdx.x * 8 + warp) * 4;   // first of 4 rows

    const float4* x0 = (const float4*)(x + (size_t)(row0 + 0) * HW);
    const float4* x1 = (const float4*)(x + (size_t)(row0 + 1) * HW);
    const float4* x2 = (const float4*)(x + (size_t)(row0 + 2) * HW);
    const float4* x3 = (const float4*)(x + (size_t)(row0 + 3) * HW);

    float acc[4][FF];
#pragma unroll
    for (int r = 0; r < 4; r++)
#pragma unroll
        for (int f = 0; f < FF; f++)
            acc[r][f] = 0.0f;

    const int J = HW / 4;                     // 784 float4 per row
    for (int j = lane; j < J; j += 32) {
        float4 a = x0[j];
        float4 b = x1[j];
        float4 c = x2[j];
        float4 d = x3[j];
#pragma unroll
        for (int f = 0; f < FF; f++) {
            float4 w = *(const float4*)(sdct + f * HW + 4 * j);
            acc[0][f] = fmaf(a.x, w.x, fmaf(a.y, w.y, fmaf(a.z, w.z, fmaf(a.w, w.w, acc[0][f]))));
            acc[1][f] = fmaf(b.x, w.x, fmaf(b.y, w.y, fmaf(b.z, w.z, fmaf(b.w, w.w, acc[1][f]))));
            acc[2][f] = fmaf(c.x, w.x, fmaf(c.y, w.y, fmaf(c.z, w.z, fmaf(c.w, w.w, acc[2][f]))));
            acc[3][f] = fmaf(d.x, w.x, fmaf(d.y, w.y, fmaf(d.z, w.z, fmaf(d.w, w.w, acc[3][f]))));
        }
    }

    // Warp reduce each of the 32 partial sums; lane 0 stores.
#pragma unroll
    for (int r = 0; r < 4; r++) {
        const int row = row0 + r;
        const int n = row / CC;
        const int c = row % CC;
#pragma unroll
        for (int f = 0; f < FF; f++) {
            float v = acc[r][f];
#pragma unroll
            for (int off = 16; off > 0; off >>= 1)
                v += __shfl_xor_sync(0xffffffffu, v, off);
            if (lane == 0)
                g_y[(size_t)n * FF * CC + f * CC + c] = v;
        }
    }
}

// ---------------------------------------------------------------------------
// Kernel 2: squeeze-excite MLP (tiny). One block per sample n.
//   z[f,o] = relu( sum_c y[n,f,c] * w1[f,o,c] )        (w1: (8,32,512))
//   s[c]   = sigmoid( sum_{f,o} z[f,o] * w2[c,f,o] )   (w2: (512,8,32))
// ---------------------------------------------------------------------------
__global__ __launch_bounds__(256, 4)
void freq_mlp_kernel(const float* __restrict__ w1,
                     const float* __restrict__ w2)
{
    __shared__ __align__(16) float zs[FF * OO];   // 256 floats

    const int n = blockIdx.x;
    const int t = threadIdx.x;

    // Phase A: 256 threads -> one (f,o) each, dot over C=512.
    {
        const int f = t >> 5;      // /32
        const int o = t & 31;
        const float4* yv = (const float4*)(g_y + (size_t)n * FF * CC + f * CC);
        const float4* wv = (const float4*)(w1 + (size_t)(f * OO + o) * CC);
        float s = 0.0f;
#pragma unroll 8
        for (int i = 0; i < CC / 4; i++) {
            float4 a = yv[i];
            float4 b = wv[i];
            s = fmaf(a.x, b.x, fmaf(a.y, b.y, fmaf(a.z, b.z, fmaf(a.w, b.w, s))));
        }
        zs[f * OO + o] = fmaxf(s, 0.0f);
    }
    __syncthreads();

    // Phase B: each thread handles 2 output channels, dot over F*O=256.
    for (int c = t; c < CC; c += 256) {
        const float4* wv = (const float4*)(w2 + (size_t)c * FF * OO);
        const float4* zv = (const float4*)zs;
        float s = 0.0f;
#pragma unroll 8
        for (int i = 0; i < (FF * OO) / 4; i++) {
            float4 a = zv[i];
            float4 b = wv[i];
            s = fmaf(a.x, b.x, fmaf(a.y, b.y, fmaf(a.z, b.z, fmaf(a.w, b.w, s))));
        }
        g_s[n * CC + c] = 1.0f / (1.0f + __expf(-s));
    }
}

// ---------------------------------------------------------------------------
// Kernel 3: broadcast channel scale (pure stream).
//   out[n,c,hw] = x[n,c,hw] * s[n,c]
// One warp per (n,c) row, float4 loads/stores. 2048 blocks x 256 thr.
// ---------------------------------------------------------------------------
__global__ __launch_bounds__(256)
void freq_scale_kernel(const float* __restrict__ x,
                       float* __restrict__ out)
{
    const int gwarp = (blockIdx.x * blockDim.x + threadIdx.x) >> 5;
    const int lane  = threadIdx.x & 31;
    if (gwarp >= ROWS) return;

    const float s = g_s[gwarp];                  // row index == n*CC + c
    const float4* xi = (const float4*)(x  + (size_t)gwarp * HW);
    float4*       oo = (float4*)(out + (size_t)gwarp * HW);

    const int J = HW / 4;                        // 784
    for (int j = lane; j < J; j += 32) {
        float4 v = xi[j];
        v.x *= s; v.y *= s; v.z *= s; v.w *= s;
        oo[j] = v;
    }
}

// ---------------------------------------------------------------------------
// Launch. Inputs (metadata order): x, dct, w1, w2. Output: fp32 (N,C,H,W).
// ---------------------------------------------------------------------------
extern "C" void kernel_launch(void* const* d_in, const int* in_sizes, int n_in,
                              void* d_out, int out_size)
{
    const float* x   = (const float*)d_in[0];
    const float* dct = (const float*)d_in[1];
    const float* w1  = (const float*)d_in[2];
    const float* w2  = (const float*)d_in[3];
    float* out = (float*)d_out;

    const int smem_bytes = FF * HW * (int)sizeof(float);   // 100,352 B
    cudaFuncSetAttribute(freq_pool_kernel,
                         cudaFuncAttributeMaxDynamicSharedMemorySize,
                         smem_bytes);

    // 512 blocks * 32 rows/block = 16384 rows
    freq_pool_kernel<<<512, 256, smem_bytes>>>(x, dct);

    freq_mlp_kernel<<<NN, 256>>>(w1, w2);

    // 16384 rows / (8 warps/block) = 2048 blocks
    freq_scale_kernel<<<2048, 256>>>(x, out);
}

// round 8
// speedup vs baseline: 1.0268x; 1.0268x over previous
#include <cuda_runtime.h>
#include <math.h>

// Problem constants
#define NN     32
#define CC     512
#define HH     56
#define WW     56
#define HW     (HH * WW)          // 3136 floats per (n,c) row
#define FF     8                  // frequencies
#define OO     32                 // C / R
#define ROWS   (NN * CC)          // 16384
#define J_ROW  (HW / 4)           // 784 float4 per row
#define HWH    (HW / 2)           // 1568  (half-row chunk, floats)
#define J_HALF (HWH / 4)          // 392 float4 per chunk per freq

// Scratch (no cudaMalloc allowed): intermediates live in device globals.
__device__ float g_y[NN * FF * CC];   // pooled DCT features (n, f, c)
__device__ float g_s[NN * CC];        // per-(n,c) sigmoid scale

// ---------------------------------------------------------------------------
// Kernel 1: multi-frequency DCT pooling.
//   y[n,f,c] = sum_{hw} x[n,c,hw] * dct[f,hw]
// v2: DCT staged in TWO 50 KB smem chunks (instead of one 100 KB block) and
// registers capped at 64 -> 4 CTAs/SM = 32 warps (was 16). 1 warp owns 4
// consecutive rows; each smem float4 is amortized over 4 rows.
// Grid: 512 blocks x 256 thr (8 warps x 4 rows = 32 rows/block).
// ---------------------------------------------------------------------------
__global__ __launch_bounds__(256, 4)
void freq_pool_kernel(const float* __restrict__ x,
                      const float* __restrict__ dct)
{
    extern __shared__ float sdct[];           // FF * HWH floats = 50,176 B

    const int warp = threadIdx.x >> 5;
    const int lane = threadIdx.x & 31;
    const int row0 = (blockIdx.x * 8 + warp) * 4;   // first of 4 rows

    // One base pointer; the other 3 rows via compile-time immediate offsets.
    const float4* xb = (const float4*)(x + (size_t)row0 * HW);

    float acc[4][FF];
#pragma unroll
    for (int r = 0; r < 4; r++)
#pragma unroll
        for (int f = 0; f < FF; f++)
            acc[r][f] = 0.0f;

#pragma unroll
    for (int chunk = 0; chunk < 2; chunk++) {
        // Cooperative load of this half of the DCT basis (8 x 392 float4).
        {
            const float4* src = (const float4*)dct;
            float4*       dst = (float4*)sdct;
            for (int i = threadIdx.x; i < FF * J_HALF; i += 256) {
                int f  = i / J_HALF;
                int jj = i - f * J_HALF;
                dst[f * J_HALF + jj] = src[f * J_ROW + chunk * J_HALF + jj];
            }
        }
        __syncthreads();

        const int jbase = chunk * J_HALF;
        for (int j = lane; j < J_HALF; j += 32) {
            const int jg = jbase + j;
            float4 a = xb[jg];
            float4 b = xb[jg + 1 * J_ROW];
            float4 c = xb[jg + 2 * J_ROW];
            float4 d = xb[jg + 3 * J_ROW];
#pragma unroll
            for (int f = 0; f < FF; f++) {
                float4 w = *(const float4*)(sdct + f * HWH + 4 * j);
                acc[0][f] = fmaf(a.x, w.x, fmaf(a.y, w.y, fmaf(a.z, w.z, fmaf(a.w, w.w, acc[0][f]))));
                acc[1][f] = fmaf(b.x, w.x, fmaf(b.y, w.y, fmaf(b.z, w.z, fmaf(b.w, w.w, acc[1][f]))));
                acc[2][f] = fmaf(c.x, w.x, fmaf(c.y, w.y, fmaf(c.z, w.z, fmaf(c.w, w.w, acc[2][f]))));
                acc[3][f] = fmaf(d.x, w.x, fmaf(d.y, w.y, fmaf(d.z, w.z, fmaf(d.w, w.w, acc[3][f]))));
            }
        }
        __syncthreads();   // protect smem before reload / after last use
    }

    // Warp reduce each of the 32 partial sums; lane 0 stores.
#pragma unroll
    for (int r = 0; r < 4; r++) {
        const int row = row0 + r;
        const int n = row / CC;
        const int c = row - n * CC;
#pragma unroll
        for (int f = 0; f < FF; f++) {
            float v = acc[r][f];
#pragma unroll
            for (int off = 16; off > 0; off >>= 1)
                v += __shfl_xor_sync(0xffffffffu, v, off);
            if (lane == 0)
                g_y[(size_t)n * FF * CC + f * CC + c] = v;
        }
    }
}

// ---------------------------------------------------------------------------
// Kernel 2: squeeze-excite MLP (tiny). One block per sample n.
//   z[f,o] = relu( sum_c y[n,f,c] * w1[f,o,c] )        (w1: (8,32,512))
//   s[c]   = sigmoid( sum_{f,o} z[f,o] * w2[c,f,o] )   (w2: (512,8,32))
// ---------------------------------------------------------------------------
__global__ __launch_bounds__(256, 4)
void freq_mlp_kernel(const float* __restrict__ w1,
                     const float* __restrict__ w2)
{
    __shared__ __align__(16) float zs[FF * OO];   // 256 floats

    const int n = blockIdx.x;
    const int t = threadIdx.x;

    // Phase A: 256 threads -> one (f,o) each, dot over C=512.
    {
        const int f = t >> 5;
        const int o = t & 31;
        const float4* yv = (const float4*)(g_y + (size_t)n * FF * CC + f * CC);
        const float4* wv = (const float4*)(w1 + (size_t)(f * OO + o) * CC);
        float s = 0.0f;
#pragma unroll 8
        for (int i = 0; i < CC / 4; i++) {
            float4 a = yv[i];
            float4 b = wv[i];
            s = fmaf(a.x, b.x, fmaf(a.y, b.y, fmaf(a.z, b.z, fmaf(a.w, b.w, s))));
        }
        zs[f * OO + o] = fmaxf(s, 0.0f);
    }
    __syncthreads();

    // Phase B: each thread handles 2 output channels, dot over F*O=256.
    for (int c = t; c < CC; c += 256) {
        const float4* wv = (const float4*)(w2 + (size_t)c * FF * OO);
        const float4* zv = (const float4*)zs;
        float s = 0.0f;
#pragma unroll 8
        for (int i = 0; i < (FF * OO) / 4; i++) {
            float4 a = zv[i];
            float4 b = wv[i];
            s = fmaf(a.x, b.x, fmaf(a.y, b.y, fmaf(a.z, b.z, fmaf(a.w, b.w, s))));
        }
        g_s[n * CC + c] = 1.0f / (1.0f + __expf(-s));
    }
}

// ---------------------------------------------------------------------------
// Kernel 3: broadcast channel scale (pure stream).
// v2: flat layout, one float4 per thread -> maximal chip-wide MLP.
//   row = float4_index / 784 (magic division); s-load is a warp broadcast.
// Grid: 50176 blocks x 256 thr (= 12,845,056 float4 exactly).
// ---------------------------------------------------------------------------
__global__ __launch_bounds__(256)
void freq_scale_kernel(const float* __restrict__ x,
                       float* __restrict__ out)
{
    const int idx = blockIdx.x * 256 + threadIdx.x;   // float4 index
    const int row = idx / J_ROW;                      // (n*CC + c)
    const float s = g_s[row];

    float4 v = ((const float4*)x)[idx];
    v.x *= s; v.y *= s; v.z *= s; v.w *= s;
    ((float4*)out)[idx] = v;
}

// ---------------------------------------------------------------------------
// Launch. Inputs (metadata order): x, dct, w1, w2. Output: fp32 (N,C,H,W).
// ---------------------------------------------------------------------------
extern "C" void kernel_launch(void* const* d_in, const int* in_sizes, int n_in,
                              void* d_out, int out_size)
{
    const float* x   = (const float*)d_in[0];
    const float* dct = (const float*)d_in[1];
    const float* w1  = (const float*)d_in[2];
    const float* w2  = (const float*)d_in[3];
    float* out = (float*)d_out;

    const int smem_bytes = FF * HWH * (int)sizeof(float);   // 50,176 B
    cudaFuncSetAttribute(freq_pool_kernel,
                         cudaFuncAttributeMaxDynamicSharedMemorySize,
                         smem_bytes);

    freq_pool_kernel<<<512, 256, smem_bytes>>>(x, dct);

    freq_mlp_kernel<<<NN, 256>>>(w1, w2);

    freq_scale_kernel<<<(ROWS * J_ROW) / 256, 256>>>(x, out);
}